// round 15
// baseline (speedup 1.0000x reference)
#include <cuda_runtime.h>
#include <cuda_fp16.h>

#define N_NODES  100000
#define N_EDGES  400000
#define N_GRAPHS 2000
#define F_EDGE   8
#define HID      16

// z-GEMM B-fragment tables, quad-packed per t-pair for LDS.128:
//   idx = (((tp*KS + ks)*32 + lane)*4 + tt*2 + r,  t = 2*tp + tt
#define B1_TILES 4
#define B1_KS    17
#define B2_TILES 2
#define B2_KS    34
#define B1TAB_N (B1_TILES * B1_KS * 2 * 32)   // 4352
#define B2TAB_N (B2_TILES * B2_KS * 2 * 32)   // 4352

#define WTILES1    (N_EDGES / 32)             // 12500 warp-tiles of 32 edges
#define EDGE_GRID  592                        // 4 CTAs/SM x 148 SMs (full residency)
#define WSTRIDE    (EDGE_GRID * 8)            // warp-slot count

// ---------------- scratch ----------------
__device__ float    g_agg1[N_NODES * 32];
__device__ float    g_agg2[N_NODES * 16];
__device__ float    g_pool[N_GRAPHS * 16];
__device__ float    g_cnt [N_GRAPHS];
__device__ unsigned g_xh2 [N_NODES * 8];    // x rows as 8 packed half2
__device__ unsigned g_h1h2[N_NODES * 16];   // h1 rows as 16 packed half2
__device__ unsigned g_B1tab[B1TAB_N];
__device__ unsigned g_B2tab[B2TAB_N];

// ---------------- helpers ----------------
__device__ __forceinline__ unsigned pack_half2(float a, float b) {
    __half2 h = __floats2half2_rn(a, b);
    return *reinterpret_cast<unsigned*>(&h);
}
__device__ __forceinline__ unsigned hmul2u(unsigned a, unsigned b) {
    __half2 r = __hmul2(*reinterpret_cast<__half2*>(&a), *reinterpret_cast<__half2*>(&b));
    return *reinterpret_cast<unsigned*>(&r);
}
__device__ __forceinline__ unsigned dup_lo(unsigned v) {
    __half2 h = __low2half2(*reinterpret_cast<__half2*>(&v));
    return *reinterpret_cast<unsigned*>(&h);
}
__device__ __forceinline__ unsigned dup_hi(unsigned v) {
    __half2 h = __high2half2(*reinterpret_cast<__half2*>(&v));
    return *reinterpret_cast<unsigned*>(&h);
}
__device__ __forceinline__ void mma16816(float c[4], const unsigned a[4], unsigned b0, unsigned b1) {
    asm volatile("mma.sync.aligned.m16n8k16.row.col.f32.f16.f16.f32 "
                 "{%0,%1,%2,%3}, {%4,%5,%6,%7}, {%8,%9}, {%0,%1,%2,%3};\n"
                 : "+f"(c[0]), "+f"(c[1]), "+f"(c[2]), "+f"(c[3])
                 : "r"(a[0]), "r"(a[1]), "r"(a[2]), "r"(a[3]),
                   "r"(b0), "r"(b1));
}
__device__ __forceinline__ void red_v2(float* p, float a, float b) {
    asm volatile("red.global.add.v2.f32 [%0], {%1, %2};" :: "l"(p), "f"(a), "f"(b) : "memory");
}

// ---------------- prep: zero + xh2 + B tables (ONE kernel) ----------------
__global__ void __launch_bounds__(256)
prep_kernel(const float* __restrict__ x,
            const float* __restrict__ w2_1, const float* __restrict__ b2_1,
            const float* __restrict__ w2_2, const float* __restrict__ b2_2)
{
    const int i = blockIdx.x * 256 + threadIdx.x;
    const float4 z = {0.f, 0.f, 0.f, 0.f};

    if (i < N_NODES * 8)  ((float4*)g_agg1)[i] = z;
    if (i < N_NODES * 4)  ((float4*)g_agg2)[i] = z;
    if (i < N_GRAPHS * 4) ((float4*)g_pool)[i] = z;
    if (i < N_GRAPHS / 4) ((float4*)g_cnt)[i]  = z;

    if (i < N_NODES * 8)
        g_xh2[i] = pack_half2(x[2 * i], x[2 * i + 1]);

    if (i < B1TAB_N) {
        const int r    = i & 1;
        const int tt   = (i >> 1) & 1;
        const int lane = (i >> 2) & 31;
        const int ks   = (i >> 7) % B1_KS;
        const int tp   = i / (B1_KS * 128);
        const int t    = tp * 2 + tt;
        const int o    = t * 8 + (lane >> 2);
        const int c    = 16 * ks + (lane & 3) * 2 + r * 8;
        float v0, v1;
        if (c < 256) { const int h = c >> 4, ii = c & 15;
            v0 = w2_1[h * 512 + ii * 32 + o]; v1 = w2_1[h * 512 + (ii + 1) * 32 + o];
        } else { const int ii = c - 256;
            v0 = b2_1[ii * 32 + o]; v1 = b2_1[(ii + 1) * 32 + o];
        }
        g_B1tab[i] = pack_half2(v0, v1);
    }
    if (i < B2TAB_N) {
        const int r    = i & 1;
        const int tt   = (i >> 1) & 1;
        const int lane = (i >> 2) & 31;
        const int ks   = (i >> 7) % B2_KS;
        const int o    = tt * 8 + (lane >> 2);
        const int c    = 16 * ks + (lane & 3) * 2 + r * 8;
        float v0, v1;
        if (c < 512) { const int h = c >> 5, ii = c & 31;
            v0 = w2_2[h * 512 + ii * 16 + o]; v1 = w2_2[h * 512 + (ii + 1) * 16 + o];
        } else { const int ii = c - 512;
            v0 = b2_2[ii * 16 + o]; v1 = b2_2[(ii + 1) * 16 + o];
        }
        g_B2tab[i] = pack_half2(v0, v1);
    }
}

// ---------------- edge1_z: persistent warps, 32-edge tiles ----------------
__global__ void __launch_bounds__(256, 4)
edge1_z_kernel(const float* __restrict__ ea,
               const int*   __restrict__ ei,
               const float* __restrict__ w1, const float* __restrict__ b1)
{
    __shared__ __align__(16) unsigned sBt[B1TAB_N];   // 17 KB
    __shared__ float    sW1[F_EDGE * HID];
    __shared__ float    sB1v[HID];
    __shared__ __align__(16) unsigned sXH[8][32][12]; // x pairs (8/edge) 12 KB
    __shared__ unsigned sH2[8][32][9];                // h packed pairs   9 KB

    const int tid  = threadIdx.x;
    const int lane = tid & 31;
    const int wid  = tid >> 5;

    for (int i = tid; i < B1TAB_N; i += 256) sBt[i] = g_B1tab[i];
    if (tid < F_EDGE * HID) sW1[tid] = w1[tid];
    if (tid < HID) sB1v[tid] = b1[tid];
    __syncthreads();

    const int row0 = lane >> 2, row1 = row0 + 8;
    const int ra0 = row0, ra1 = row1;
    const int rb0 = row0 + 16, rb1 = row1 + 16;
    const int k0 = (lane & 3) * 2;
    const int p  = k0 >> 1;

    for (int wtile = blockIdx.x * 8 + wid; wtile < WTILES1; wtile += WSTRIDE) {
        const int e0 = wtile * 32;

        const int src_reg = ei[e0 + lane];
        const int dst_reg = ei[N_EDGES + e0 + lane];

        #pragma unroll
        for (int it = 0; it < 2; it++) {
            const int e = it * 16 + (lane >> 1), part = lane & 1;
            const int s = __shfl_sync(0xffffffffu, src_reg, e);
            const uint4 v = *(const uint4*)(g_xh2 + (size_t)s * 8 + part * 4);
            *(uint4*)&sXH[wid][e][part * 4] = v;
        }
        {
            const float4 v0 = *(const float4*)(ea + (size_t)(e0 + lane) * 8);
            const float4 v1 = *(const float4*)(ea + (size_t)(e0 + lane) * 8 + 4);
            const float eav[8] = {v0.x, v0.y, v0.z, v0.w, v1.x, v1.y, v1.z, v1.w};
            #pragma unroll
            for (int k = 0; k < 8; k++) {
                float s0 = sB1v[2*k], s1 = sB1v[2*k + 1];
                #pragma unroll
                for (int j = 0; j < F_EDGE; j++) {
                    s0 += eav[j] * sW1[j * HID + 2*k];
                    s1 += eav[j] * sW1[j * HID + 2*k + 1];
                }
                sH2[wid][lane][k] = pack_half2(fmaxf(s0, 0.f), fmaxf(s1, 0.f));
            }
        }
        __syncwarp();

        const unsigned xa0 = sXH[wid][ra0][p], xa1 = sXH[wid][ra0][p + 4];
        const unsigned xa2 = sXH[wid][ra1][p], xa3 = sXH[wid][ra1][p + 4];
        const unsigned xb0 = sXH[wid][rb0][p], xb1 = sXH[wid][rb0][p + 4];
        const unsigned xb2 = sXH[wid][rb1][p], xb3 = sXH[wid][rb1][p + 4];

        float accA[4][4] = {}, accB[4][4] = {};
        #pragma unroll
        for (int k = 0; k < 8; k++) {
            const unsigned pa0 = sH2[wid][ra0][k], pa1 = sH2[wid][ra1][k];
            const unsigned pb0 = sH2[wid][rb0][k], pb1 = sH2[wid][rb1][k];
            #pragma unroll
            for (int hf = 0; hf < 2; hf++) {
                const int ks = 2*k + hf;
                const unsigned ha0 = hf ? dup_hi(pa0) : dup_lo(pa0);
                const unsigned ha1 = hf ? dup_hi(pa1) : dup_lo(pa1);
                const unsigned hb0 = hf ? dup_hi(pb0) : dup_lo(pb0);
                const unsigned hb1 = hf ? dup_hi(pb1) : dup_lo(pb1);
                const unsigned aA[4] = {hmul2u(ha0, xa0), hmul2u(ha1, xa2),
                                        hmul2u(ha0, xa1), hmul2u(ha1, xa3)};
                const unsigned aB[4] = {hmul2u(hb0, xb0), hmul2u(hb1, xb2),
                                        hmul2u(hb0, xb1), hmul2u(hb1, xb3)};
                #pragma unroll
                for (int tp = 0; tp < 2; tp++) {
                    const uint4 bv = *(const uint4*)&sBt[((tp * B1_KS + ks) * 32 + lane) * 4];
                    mma16816(accA[2*tp],     aA, bv.x, bv.y);
                    mma16816(accA[2*tp + 1], aA, bv.z, bv.w);
                    mma16816(accB[2*tp],     aB, bv.x, bv.y);
                    mma16816(accB[2*tp + 1], aB, bv.z, bv.w);
                }
            }
        }
        {   // bias k-step (z = x)
            const unsigned aA[4] = {xa0, xa2, xa1, xa3};
            const unsigned aB[4] = {xb0, xb2, xb1, xb3};
            #pragma unroll
            for (int tp = 0; tp < 2; tp++) {
                const uint4 bv = *(const uint4*)&sBt[((tp * B1_KS + 16) * 32 + lane) * 4];
                mma16816(accA[2*tp],     aA, bv.x, bv.y);
                mma16816(accA[2*tp + 1], aA, bv.z, bv.w);
                mma16816(accB[2*tp],     aB, bv.x, bv.y);
                mma16816(accB[2*tp + 1], aB, bv.z, bv.w);
            }
        }

        const int dA0 = __shfl_sync(0xffffffffu, dst_reg, ra0);
        const int dA1 = __shfl_sync(0xffffffffu, dst_reg, ra1);
        const int dB0 = __shfl_sync(0xffffffffu, dst_reg, rb0);
        const int dB1 = __shfl_sync(0xffffffffu, dst_reg, rb1);
        #pragma unroll
        for (int t = 0; t < 4; t++) {
            const int o = t * 8 + k0;
            red_v2(&g_agg1[(size_t)dA0 * 32 + o], accA[t][0], accA[t][1]);
            red_v2(&g_agg1[(size_t)dA1 * 32 + o], accA[t][2], accA[t][3]);
            red_v2(&g_agg1[(size_t)dB0 * 32 + o], accB[t][0], accB[t][1]);
            red_v2(&g_agg1[(size_t)dB1 * 32 + o], accB[t][2], accB[t][3]);
        }
        __syncwarp();
    }
}

// ---------------- node1: h1 = relu(x@root1 + agg1 + bias1) -> fp16 pairs ----------------
__global__ void __launch_bounds__(256)
node1_kernel(const float* __restrict__ x,
             const float* __restrict__ root1, const float* __restrict__ bias1)
{
    __shared__ float sR1[16 * 32];
    __shared__ float sB1[32];
    __shared__ float sX[16][17];

    const int tid = threadIdx.x;
    const int nb  = blockIdx.x * 16;

    for (int i = tid; i < 512; i += 256) sR1[i] = root1[i];
    if (tid < 32) sB1[tid] = bias1[tid];
    if (tid < 256) {
        const int nl = tid >> 4, i = tid & 15;
        sX[nl][i] = x[(size_t)(nb + nl) * 16 + i];
    }
    __syncthreads();

    const int nl = tid >> 4;
    const int pr = tid & 15;
    const int n  = nb + nl;
    const int o0 = 2 * pr, o1 = o0 + 1;

    float a0 = sB1[o0] + g_agg1[(size_t)n * 32 + o0];
    float a1 = sB1[o1] + g_agg1[(size_t)n * 32 + o1];
    #pragma unroll
    for (int i = 0; i < 16; i++) {
        const float xi = sX[nl][i];
        a0 += xi * sR1[i * 32 + o0];
        a1 += xi * sR1[i * 32 + o1];
    }
    g_h1h2[(size_t)n * 16 + pr] = pack_half2(fmaxf(a0, 0.f), fmaxf(a1, 0.f));
}

// ---------------- edge2_z: persistent warps, 32-edge tiles ----------------
__global__ void __launch_bounds__(256, 4)
edge2_z_kernel(const float* __restrict__ ea,
               const int*   __restrict__ ei,
               const float* __restrict__ w1, const float* __restrict__ b1)
{
    __shared__ __align__(16) unsigned sBt[B2TAB_N];   // 17 KB
    __shared__ float    sW1[F_EDGE * HID];
    __shared__ float    sB1v[HID];
    __shared__ __align__(16) unsigned sHH[8][32][20]; // h1 pairs (16/edge) 20.5 KB
    __shared__ unsigned sH2[8][32][9];                // h packed pairs     9 KB

    const int tid  = threadIdx.x;
    const int lane = tid & 31;
    const int wid  = tid >> 5;

    for (int i = tid; i < B2TAB_N; i += 256) sBt[i] = g_B2tab[i];
    if (tid < F_EDGE * HID) sW1[tid] = w1[tid];
    if (tid < HID) sB1v[tid] = b1[tid];
    __syncthreads();

    const int row0 = lane >> 2, row1 = row0 + 8;
    const int ra0 = row0, ra1 = row1;
    const int rb0 = row0 + 16, rb1 = row1 + 16;
    const int k0 = (lane & 3) * 2;
    const int p  = k0 >> 1;

    for (int wtile = blockIdx.x * 8 + wid; wtile < WTILES1; wtile += WSTRIDE) {
        const int e0 = wtile * 32;

        const int src_reg = ei[e0 + lane];
        const int dst_reg = ei[N_EDGES + e0 + lane];

        #pragma unroll
        for (int it = 0; it < 2; it++) {
            const int e = it * 16 + (lane >> 1), part = lane & 1;
            const int s = __shfl_sync(0xffffffffu, src_reg, e);
            const uint4 va = *(const uint4*)(g_h1h2 + (size_t)s * 16 + part * 8);
            const uint4 vb = *(const uint4*)(g_h1h2 + (size_t)s * 16 + part * 8 + 4);
            *(uint4*)&sHH[wid][e][part * 8]     = va;
            *(uint4*)&sHH[wid][e][part * 8 + 4] = vb;
        }
        {
            const float4 v0 = *(const float4*)(ea + (size_t)(e0 + lane) * 8);
            const float4 v1 = *(const float4*)(ea + (size_t)(e0 + lane) * 8 + 4);
            const float eav[8] = {v0.x, v0.y, v0.z, v0.w, v1.x, v1.y, v1.z, v1.w};
            #pragma unroll
            for (int k = 0; k < 8; k++) {
                float s0 = sB1v[2*k], s1 = sB1v[2*k + 1];
                #pragma unroll
                for (int j = 0; j < F_EDGE; j++) {
                    s0 += eav[j] * sW1[j * HID + 2*k];
                    s1 += eav[j] * sW1[j * HID + 2*k + 1];
                }
                sH2[wid][lane][k] = pack_half2(fmaxf(s0, 0.f), fmaxf(s1, 0.f));
            }
        }
        __syncwarp();

        const unsigned xa[4] = {sHH[wid][ra0][p], sHH[wid][ra0][p + 4],
                                sHH[wid][ra0][p + 8], sHH[wid][ra0][p + 12]};
        const unsigned ya[4] = {sHH[wid][ra1][p], sHH[wid][ra1][p + 4],
                                sHH[wid][ra1][p + 8], sHH[wid][ra1][p + 12]};
        const unsigned xb[4] = {sHH[wid][rb0][p], sHH[wid][rb0][p + 4],
                                sHH[wid][rb0][p + 8], sHH[wid][rb0][p + 12]};
        const unsigned yb[4] = {sHH[wid][rb1][p], sHH[wid][rb1][p + 4],
                                sHH[wid][rb1][p + 8], sHH[wid][rb1][p + 12]};

        float accA[2][4] = {}, accB[2][4] = {};
        #pragma unroll
        for (int j = 0; j < 8; j++) {
            const unsigned pa0 = sH2[wid][ra0][j], pa1 = sH2[wid][ra1][j];
            const unsigned pb0 = sH2[wid][rb0][j], pb1 = sH2[wid][rb1][j];
            #pragma unroll
            for (int mh = 0; mh < 2; mh++) {
                const int m = 2*j + mh;
                const unsigned ha0 = mh ? dup_hi(pa0) : dup_lo(pa0);
                const unsigned ha1 = mh ? dup_hi(pa1) : dup_lo(pa1);
                const unsigned hb0 = mh ? dup_hi(pb0) : dup_lo(pb0);
                const unsigned hb1 = mh ? dup_hi(pb1) : dup_lo(pb1);
                #pragma unroll
                for (int half = 0; half < 2; half++) {   // ks = 2m + half
                    const unsigned aA[4] = {hmul2u(ha0, xa[2*half]), hmul2u(ha1, ya[2*half]),
                                            hmul2u(ha0, xa[2*half+1]), hmul2u(ha1, ya[2*half+1])};
                    const unsigned aB[4] = {hmul2u(hb0, xb[2*half]), hmul2u(hb1, yb[2*half]),
                                            hmul2u(hb0, xb[2*half+1]), hmul2u(hb1, yb[2*half+1])};
                    const uint4 bv = *(const uint4*)&sBt[((2*m + half) * 32 + lane) * 4];
                    mma16816(accA[0], aA, bv.x, bv.y);
                    mma16816(accA[1], aA, bv.z, bv.w);
                    mma16816(accB[0], aB, bv.x, bv.y);
                    mma16816(accB[1], aB, bv.z, bv.w);
                }
            }
        }
        #pragma unroll
        for (int half = 0; half < 2; half++) {   // bias ks = 32 + half
            const unsigned aA[4] = {xa[2*half], ya[2*half], xa[2*half+1], ya[2*half+1]};
            const unsigned aB[4] = {xb[2*half], yb[2*half], xb[2*half+1], yb[2*half+1]};
            const uint4 bv = *(const uint4*)&sBt[((32 + half) * 32 + lane) * 4];
            mma16816(accA[0], aA, bv.x, bv.y);
            mma16816(accA[1], aA, bv.z, bv.w);
            mma16816(accB[0], aB, bv.x, bv.y);
            mma16816(accB[1], aB, bv.z, bv.w);
        }

        const int dA0 = __shfl_sync(0xffffffffu, dst_reg, ra0);
        const int dA1 = __shfl_sync(0xffffffffu, dst_reg, ra1);
        const int dB0 = __shfl_sync(0xffffffffu, dst_reg, rb0);
        const int dB1 = __shfl_sync(0xffffffffu, dst_reg, rb1);
        #pragma unroll
        for (int t = 0; t < 2; t++) {
            const int o = t * 8 + k0;
            red_v2(&g_agg2[(size_t)dA0 * 16 + o], accA[t][0], accA[t][1]);
            red_v2(&g_agg2[(size_t)dA1 * 16 + o], accA[t][2], accA[t][3]);
            red_v2(&g_agg2[(size_t)dB0 * 16 + o], accB[t][0], accB[t][1]);
            red_v2(&g_agg2[(size_t)dB1 * 16 + o], accB[t][2], accB[t][3]);
        }
        __syncwarp();
    }
}

// ---------------- fused node2 + pool (sorted-batch atomic pairing) ----------------
__global__ void __launch_bounds__(256)
node2_pool_kernel(const int* __restrict__ batch,
                  const float* __restrict__ root2, const float* __restrict__ bias2)
{
    __shared__ float sR2[32 * 16];
    __shared__ float sB2v[16];
    for (int idx = threadIdx.x; idx < 512; idx += 256) sR2[idx] = root2[idx];
    if (threadIdx.x < 16) sB2v[threadIdx.x] = bias2[threadIdx.x];
    __syncthreads();

    const int w = (blockIdx.x * 256 + threadIdx.x) >> 5;
    const int lane = threadIdx.x & 31;
    const int half = lane >> 4;
    const int o = lane & 15;
    const int n = 2 * w + half;

    const unsigned hp = g_h1h2[(size_t)n * 16 + o];

    float acc = sB2v[o] + g_agg2[(size_t)n * 16 + o];
    #pragma unroll
    for (int i = 0; i < 16; i++) {
        const unsigned pi = __shfl_sync(0xffffffffu, hp, i, 16);
        const float2 f = __half22float2(*reinterpret_cast<const __half2*>(&pi));
        acc += f.x * sR2[(2 * i) * 16 + o] + f.y * sR2[(2 * i + 1) * 16 + o];
    }

    const float v = fmaxf(acc, 0.f);
    const int g = batch[n];
    const int g_other = __shfl_xor_sync(0xffffffffu, g, 16);
    const float v_other = __shfl_xor_sync(0xffffffffu, v, 16);
    if (g == g_other) {
        if (half == 0) {
            atomicAdd(&g_pool[g * 16 + o], v + v_other);
            if (o == 0) atomicAdd(&g_cnt[g], 2.0f);
        }
    } else {
        atomicAdd(&g_pool[g * 16 + o], v);
        if (o == 0) atomicAdd(&g_cnt[g], 1.0f);
    }
}

// ---------------- readout MLP ----------------
__global__ void readout_kernel(const float* __restrict__ l1w, const float* __restrict__ l1b,
                               const float* __restrict__ l2w, const float* __restrict__ l2b,
                               float* __restrict__ out)
{
    const int g = blockIdx.x * blockDim.x + threadIdx.x;
    if (g >= N_GRAPHS) return;
    const float inv = 1.0f / fmaxf(g_cnt[g], 1.0f);
    float p[16];
    #pragma unroll
    for (int o = 0; o < 16; o++) p[o] = g_pool[g * 16 + o] * inv;
    float acc = l2b[0];
    #pragma unroll
    for (int j = 0; j < 8; j++) {
        float s = l1b[j];
        #pragma unroll
        for (int o = 0; o < 16; o++) s += p[o] * l1w[o * 8 + j];
        acc += fmaxf(s, 0.f) * l2w[j];
    }
    out[g] = acc;
}

// ---------------- launch ----------------
extern "C" void kernel_launch(void* const* d_in, const int* in_sizes, int n_in,
                              void* d_out, int out_size)
{
    const float* x      = (const float*)d_in[0];
    const float* ea     = (const float*)d_in[1];
    const int*   ei     = (const int*)  d_in[2];
    const int*   batch  = (const int*)  d_in[3];
    const float* nn1_w1 = (const float*)d_in[4];
    const float* nn1_b1 = (const float*)d_in[5];
    const float* nn1_w2 = (const float*)d_in[6];
    const float* nn1_b2 = (const float*)d_in[7];
    const float* root1  = (const float*)d_in[8];
    const float* bias1  = (const float*)d_in[9];
    const float* nn2_w1 = (const float*)d_in[10];
    const float* nn2_b1 = (const float*)d_in[11];
    const float* nn2_w2 = (const float*)d_in[12];
    const float* nn2_b2 = (const float*)d_in[13];
    const float* root2  = (const float*)d_in[14];
    const float* bias2  = (const float*)d_in[15];
    const float* lin1_w = (const float*)d_in[16];
    const float* lin1_b = (const float*)d_in[17];
    const float* lin2_w = (const float*)d_in[18];
    const float* lin2_b = (const float*)d_in[19];
    float* out = (float*)d_out;

    prep_kernel<<<(N_NODES * 8 + 255) / 256, 256>>>(x, nn1_w2, nn1_b2, nn2_w2, nn2_b2);

    // persistent edge kernels: exactly one full residency wave (592 blocks)
    edge1_z_kernel<<<EDGE_GRID, 256>>>(ea, ei, nn1_w1, nn1_b1);
    node1_kernel<<<N_NODES / 16, 256>>>(x, root1, bias1);
    edge2_z_kernel<<<EDGE_GRID, 256>>>(ea, ei, nn2_w1, nn2_b1);
    node2_pool_kernel<<<(N_NODES / 2 * 32) / 256, 256>>>(batch, root2, bias2);
    readout_kernel<<<(N_GRAPHS + 255) / 256, 256>>>(lin1_w, lin1_b, lin2_w, lin2_b, out);
}

// round 16
// speedup vs baseline: 1.1438x; 1.1438x over previous
#include <cuda_runtime.h>
#include <cuda_fp16.h>

#define N_NODES  100000
#define N_EDGES  400000
#define N_GRAPHS 2000
#define F_EDGE   8
#define HID      16

// z-GEMM B-fragment tables, quad-packed per t-pair for LDS.128:
//   idx = (((tp*KS + ks)*32 + lane)*4 + tt*2 + r,  t = 2*tp + tt
#define B1_TILES 4
#define B1_KS    17
#define B2_TILES 2
#define B2_KS    34
#define B1TAB_N (B1_TILES * B1_KS * 2 * 32)   // 4352
#define B2TAB_N (B2_TILES * B2_KS * 2 * 32)   // 4352

#define WTILES1 (N_EDGES / 32)                // 12500 warp-tiles of 32 edges

// ---------------- scratch ----------------
__device__ float    g_agg1[N_NODES * 32];
__device__ float    g_agg2[N_NODES * 16];
__device__ float    g_pool[N_GRAPHS * 16];
__device__ float    g_cnt [N_GRAPHS];
__device__ unsigned g_xh2 [N_NODES * 8];    // x rows as 8 packed half2
__device__ unsigned g_h1h2[N_NODES * 16];   // h1 rows as 16 packed half2
__device__ unsigned g_B1tab[B1TAB_N];
__device__ unsigned g_B2tab[B2TAB_N];

// ---------------- helpers ----------------
__device__ __forceinline__ unsigned pack_half2(float a, float b) {
    __half2 h = __floats2half2_rn(a, b);
    return *reinterpret_cast<unsigned*>(&h);
}
__device__ __forceinline__ unsigned hmul2u(unsigned a, unsigned b) {
    __half2 r = __hmul2(*reinterpret_cast<__half2*>(&a), *reinterpret_cast<__half2*>(&b));
    return *reinterpret_cast<unsigned*>(&r);
}
__device__ __forceinline__ unsigned dup_lo(unsigned v) {
    __half2 h = __low2half2(*reinterpret_cast<__half2*>(&v));
    return *reinterpret_cast<unsigned*>(&h);
}
__device__ __forceinline__ unsigned dup_hi(unsigned v) {
    __half2 h = __high2half2(*reinterpret_cast<__half2*>(&v));
    return *reinterpret_cast<unsigned*>(&h);
}
__device__ __forceinline__ void mma16816(float c[4], const unsigned a[4], unsigned b0, unsigned b1) {
    asm volatile("mma.sync.aligned.m16n8k16.row.col.f32.f16.f16.f32 "
                 "{%0,%1,%2,%3}, {%4,%5,%6,%7}, {%8,%9}, {%0,%1,%2,%3};\n"
                 : "+f"(c[0]), "+f"(c[1]), "+f"(c[2]), "+f"(c[3])
                 : "r"(a[0]), "r"(a[1]), "r"(a[2]), "r"(a[3]),
                   "r"(b0), "r"(b1));
}
__device__ __forceinline__ void red_v2(float* p, float a, float b) {
    asm volatile("red.global.add.v2.f32 [%0], {%1, %2};" :: "l"(p), "f"(a), "f"(b) : "memory");
}

// ---------------- prep: zero + xh2 + B tables (ONE kernel, no hid) ----------------
__global__ void __launch_bounds__(256)
prep_kernel(const float* __restrict__ x,
            const float* __restrict__ w2_1, const float* __restrict__ b2_1,
            const float* __restrict__ w2_2, const float* __restrict__ b2_2)
{
    const int i = blockIdx.x * 256 + threadIdx.x;
    const float4 z = {0.f, 0.f, 0.f, 0.f};

    if (i < N_NODES * 8)  ((float4*)g_agg1)[i] = z;
    if (i < N_NODES * 4)  ((float4*)g_agg2)[i] = z;
    if (i < N_GRAPHS * 4) ((float4*)g_pool)[i] = z;
    if (i < N_GRAPHS / 4) ((float4*)g_cnt)[i]  = z;

    if (i < N_NODES * 8)
        g_xh2[i] = pack_half2(x[2 * i], x[2 * i + 1]);

    if (i < B1TAB_N) {
        const int r    = i & 1;
        const int tt   = (i >> 1) & 1;
        const int lane = (i >> 2) & 31;
        const int ks   = (i >> 7) % B1_KS;
        const int tp   = i / (B1_KS * 128);
        const int t    = tp * 2 + tt;
        const int o    = t * 8 + (lane >> 2);
        const int c    = 16 * ks + (lane & 3) * 2 + r * 8;
        float v0, v1;
        if (c < 256) { const int h = c >> 4, ii = c & 15;
            v0 = w2_1[h * 512 + ii * 32 + o]; v1 = w2_1[h * 512 + (ii + 1) * 32 + o];
        } else { const int ii = c - 256;
            v0 = b2_1[ii * 32 + o]; v1 = b2_1[(ii + 1) * 32 + o];
        }
        g_B1tab[i] = pack_half2(v0, v1);
    }
    if (i < B2TAB_N) {
        const int r    = i & 1;
        const int tt   = (i >> 1) & 1;
        const int lane = (i >> 2) & 31;
        const int ks   = (i >> 7) % B2_KS;
        const int o    = tt * 8 + (lane >> 2);
        const int c    = 16 * ks + (lane & 3) * 2 + r * 8;
        float v0, v1;
        if (c < 512) { const int h = c >> 5, ii = c & 31;
            v0 = w2_2[h * 512 + ii * 16 + o]; v1 = w2_2[h * 512 + (ii + 1) * 16 + o];
        } else { const int ii = c - 512;
            v0 = b2_2[ii * 16 + o]; v1 = b2_2[(ii + 1) * 16 + o];
        }
        g_B2tab[i] = pack_half2(v0, v1);
    }
}

// ---------------- edge1_z: warp per 32-edge tile (inline hid — R12-verified) ----------------
__global__ void __launch_bounds__(256, 4)
edge1_z_kernel(const float* __restrict__ ea,
               const int*   __restrict__ ei,
               const float* __restrict__ w1, const float* __restrict__ b1)
{
    __shared__ __align__(16) unsigned sBt[B1TAB_N];   // 17 KB
    __shared__ float    sW1[F_EDGE * HID];
    __shared__ float    sB1v[HID];
    __shared__ __align__(16) unsigned sXH[8][32][12]; // x pairs (8/edge) 12 KB
    __shared__ unsigned sH2[8][32][9];                // h packed pairs   9 KB

    const int tid  = threadIdx.x;
    const int lane = tid & 31;
    const int wid  = tid >> 5;

    for (int i = tid; i < B1TAB_N; i += 256) sBt[i] = g_B1tab[i];
    if (tid < F_EDGE * HID) sW1[tid] = w1[tid];
    if (tid < HID) sB1v[tid] = b1[tid];
    __syncthreads();

    const int wtile = blockIdx.x * 8 + wid;
    if (wtile >= WTILES1) return;
    const int e0 = wtile * 32;

    const int src_reg = ei[e0 + lane];
    const int dst_reg = ei[N_EDGES + e0 + lane];

    #pragma unroll
    for (int it = 0; it < 2; it++) {
        const int e = it * 16 + (lane >> 1), part = lane & 1;
        const int s = __shfl_sync(0xffffffffu, src_reg, e);
        const uint4 v = *(const uint4*)(g_xh2 + (size_t)s * 8 + part * 4);
        *(uint4*)&sXH[wid][e][part * 4] = v;
    }
    {
        const float4 v0 = *(const float4*)(ea + (size_t)(e0 + lane) * 8);
        const float4 v1 = *(const float4*)(ea + (size_t)(e0 + lane) * 8 + 4);
        const float eav[8] = {v0.x, v0.y, v0.z, v0.w, v1.x, v1.y, v1.z, v1.w};
        #pragma unroll
        for (int k = 0; k < 8; k++) {
            float s0 = sB1v[2*k], s1 = sB1v[2*k + 1];
            #pragma unroll
            for (int j = 0; j < F_EDGE; j++) {
                s0 += eav[j] * sW1[j * HID + 2*k];
                s1 += eav[j] * sW1[j * HID + 2*k + 1];
            }
            sH2[wid][lane][k] = pack_half2(fmaxf(s0, 0.f), fmaxf(s1, 0.f));
        }
    }
    __syncwarp();

    const int row0 = lane >> 2, row1 = row0 + 8;
    const int ra0 = row0, ra1 = row1;
    const int rb0 = row0 + 16, rb1 = row1 + 16;
    const int k0 = (lane & 3) * 2;
    const int p  = k0 >> 1;

    const unsigned xa0 = sXH[wid][ra0][p], xa1 = sXH[wid][ra0][p + 4];
    const unsigned xa2 = sXH[wid][ra1][p], xa3 = sXH[wid][ra1][p + 4];
    const unsigned xb0 = sXH[wid][rb0][p], xb1 = sXH[wid][rb0][p + 4];
    const unsigned xb2 = sXH[wid][rb1][p], xb3 = sXH[wid][rb1][p + 4];

    float accA[4][4] = {}, accB[4][4] = {};
    #pragma unroll
    for (int k = 0; k < 8; k++) {
        const unsigned pa0 = sH2[wid][ra0][k], pa1 = sH2[wid][ra1][k];
        const unsigned pb0 = sH2[wid][rb0][k], pb1 = sH2[wid][rb1][k];
        #pragma unroll
        for (int hf = 0; hf < 2; hf++) {
            const int ks = 2*k + hf;
            const unsigned ha0 = hf ? dup_hi(pa0) : dup_lo(pa0);
            const unsigned ha1 = hf ? dup_hi(pa1) : dup_lo(pa1);
            const unsigned hb0 = hf ? dup_hi(pb0) : dup_lo(pb0);
            const unsigned hb1 = hf ? dup_hi(pb1) : dup_lo(pb1);
            const unsigned aA[4] = {hmul2u(ha0, xa0), hmul2u(ha1, xa2),
                                    hmul2u(ha0, xa1), hmul2u(ha1, xa3)};
            const unsigned aB[4] = {hmul2u(hb0, xb0), hmul2u(hb1, xb2),
                                    hmul2u(hb0, xb1), hmul2u(hb1, xb3)};
            #pragma unroll
            for (int tp = 0; tp < 2; tp++) {
                const uint4 bv = *(const uint4*)&sBt[((tp * B1_KS + ks) * 32 + lane) * 4];
                mma16816(accA[2*tp],     aA, bv.x, bv.y);
                mma16816(accA[2*tp + 1], aA, bv.z, bv.w);
                mma16816(accB[2*tp],     aB, bv.x, bv.y);
                mma16816(accB[2*tp + 1], aB, bv.z, bv.w);
            }
        }
    }
    {   // bias k-step (z = x)
        const unsigned aA[4] = {xa0, xa2, xa1, xa3};
        const unsigned aB[4] = {xb0, xb2, xb1, xb3};
        #pragma unroll
        for (int tp = 0; tp < 2; tp++) {
            const uint4 bv = *(const uint4*)&sBt[((tp * B1_KS + 16) * 32 + lane) * 4];
            mma16816(accA[2*tp],     aA, bv.x, bv.y);
            mma16816(accA[2*tp + 1], aA, bv.z, bv.w);
            mma16816(accB[2*tp],     aB, bv.x, bv.y);
            mma16816(accB[2*tp + 1], aB, bv.z, bv.w);
        }
    }

    const int dA0 = __shfl_sync(0xffffffffu, dst_reg, ra0);
    const int dA1 = __shfl_sync(0xffffffffu, dst_reg, ra1);
    const int dB0 = __shfl_sync(0xffffffffu, dst_reg, rb0);
    const int dB1 = __shfl_sync(0xffffffffu, dst_reg, rb1);
    #pragma unroll
    for (int t = 0; t < 4; t++) {
        const int o = t * 8 + k0;
        red_v2(&g_agg1[(size_t)dA0 * 32 + o], accA[t][0], accA[t][1]);
        red_v2(&g_agg1[(size_t)dA1 * 32 + o], accA[t][2], accA[t][3]);
        red_v2(&g_agg1[(size_t)dB0 * 32 + o], accB[t][0], accB[t][1]);
        red_v2(&g_agg1[(size_t)dB1 * 32 + o], accB[t][2], accB[t][3]);
    }
}

// ---------------- node1: h1 = relu(x@root1 + agg1 + bias1) -> fp16 pairs ----------------
__global__ void __launch_bounds__(256)
node1_kernel(const float* __restrict__ x,
             const float* __restrict__ root1, const float* __restrict__ bias1)
{
    __shared__ float sR1[16 * 32];
    __shared__ float sB1[32];
    __shared__ float sX[16][17];

    const int tid = threadIdx.x;
    const int nb  = blockIdx.x * 16;

    for (int i = tid; i < 512; i += 256) sR1[i] = root1[i];
    if (tid < 32) sB1[tid] = bias1[tid];
    if (tid < 256) {
        const int nl = tid >> 4, i = tid & 15;
        sX[nl][i] = x[(size_t)(nb + nl) * 16 + i];
    }
    __syncthreads();

    const int nl = tid >> 4;
    const int pr = tid & 15;
    const int n  = nb + nl;
    const int o0 = 2 * pr, o1 = o0 + 1;

    float a0 = sB1[o0] + g_agg1[(size_t)n * 32 + o0];
    float a1 = sB1[o1] + g_agg1[(size_t)n * 32 + o1];
    #pragma unroll
    for (int i = 0; i < 16; i++) {
        const float xi = sX[nl][i];
        a0 += xi * sR1[i * 32 + o0];
        a1 += xi * sR1[i * 32 + o1];
    }
    g_h1h2[(size_t)n * 16 + pr] = pack_half2(fmaxf(a0, 0.f), fmaxf(a1, 0.f));
}

// ---------------- edge2_z: warp per 32-edge tile (static smem, 47.7 KB — R12-verified) ----------------
__global__ void __launch_bounds__(256, 4)
edge2_z_kernel(const float* __restrict__ ea,
               const int*   __restrict__ ei,
               const float* __restrict__ w1, const float* __restrict__ b1)
{
    __shared__ __align__(16) unsigned sBt[B2TAB_N];   // 17 KB
    __shared__ float    sW1[F_EDGE * HID];
    __shared__ float    sB1v[HID];
    __shared__ __align__(16) unsigned sHH[8][32][20]; // h1 pairs (16/edge) 20.5 KB
    __shared__ unsigned sH2[8][32][9];                // h packed pairs     9 KB

    const int tid  = threadIdx.x;
    const int lane = tid & 31;
    const int wid  = tid >> 5;

    for (int i = tid; i < B2TAB_N; i += 256) sBt[i] = g_B2tab[i];
    if (tid < F_EDGE * HID) sW1[tid] = w1[tid];
    if (tid < HID) sB1v[tid] = b1[tid];
    __syncthreads();

    const int wtile = blockIdx.x * 8 + wid;
    if (wtile >= WTILES1) return;
    const int e0 = wtile * 32;

    const int src_reg = ei[e0 + lane];
    const int dst_reg = ei[N_EDGES + e0 + lane];

    #pragma unroll
    for (int it = 0; it < 2; it++) {
        const int e = it * 16 + (lane >> 1), part = lane & 1;
        const int s = __shfl_sync(0xffffffffu, src_reg, e);
        const uint4 va = *(const uint4*)(g_h1h2 + (size_t)s * 16 + part * 8);
        const uint4 vb = *(const uint4*)(g_h1h2 + (size_t)s * 16 + part * 8 + 4);
        *(uint4*)&sHH[wid][e][part * 8]     = va;
        *(uint4*)&sHH[wid][e][part * 8 + 4] = vb;
    }
    {
        const float4 v0 = *(const float4*)(ea + (size_t)(e0 + lane) * 8);
        const float4 v1 = *(const float4*)(ea + (size_t)(e0 + lane) * 8 + 4);
        const float eav[8] = {v0.x, v0.y, v0.z, v0.w, v1.x, v1.y, v1.z, v1.w};
        #pragma unroll
        for (int k = 0; k < 8; k++) {
            float s0 = sB1v[2*k], s1 = sB1v[2*k + 1];
            #pragma unroll
            for (int j = 0; j < F_EDGE; j++) {
                s0 += eav[j] * sW1[j * HID + 2*k];
                s1 += eav[j] * sW1[j * HID + 2*k + 1];
            }
            sH2[wid][lane][k] = pack_half2(fmaxf(s0, 0.f), fmaxf(s1, 0.f));
        }
    }
    __syncwarp();

    const int row0 = lane >> 2, row1 = row0 + 8;
    const int ra0 = row0, ra1 = row1;
    const int rb0 = row0 + 16, rb1 = row1 + 16;
    const int k0 = (lane & 3) * 2;
    const int p  = k0 >> 1;

    const unsigned xa[4] = {sHH[wid][ra0][p], sHH[wid][ra0][p + 4],
                            sHH[wid][ra0][p + 8], sHH[wid][ra0][p + 12]};
    const unsigned ya[4] = {sHH[wid][ra1][p], sHH[wid][ra1][p + 4],
                            sHH[wid][ra1][p + 8], sHH[wid][ra1][p + 12]};
    const unsigned xb[4] = {sHH[wid][rb0][p], sHH[wid][rb0][p + 4],
                            sHH[wid][rb0][p + 8], sHH[wid][rb0][p + 12]};
    const unsigned yb[4] = {sHH[wid][rb1][p], sHH[wid][rb1][p + 4],
                            sHH[wid][rb1][p + 8], sHH[wid][rb1][p + 12]};

    float accA[2][4] = {}, accB[2][4] = {};
    #pragma unroll
    for (int j = 0; j < 8; j++) {
        const unsigned pa0 = sH2[wid][ra0][j], pa1 = sH2[wid][ra1][j];
        const unsigned pb0 = sH2[wid][rb0][j], pb1 = sH2[wid][rb1][j];
        #pragma unroll
        for (int mh = 0; mh < 2; mh++) {
            const int m = 2*j + mh;
            const unsigned ha0 = mh ? dup_hi(pa0) : dup_lo(pa0);
            const unsigned ha1 = mh ? dup_hi(pa1) : dup_lo(pa1);
            const unsigned hb0 = mh ? dup_hi(pb0) : dup_lo(pb0);
            const unsigned hb1 = mh ? dup_hi(pb1) : dup_lo(pb1);
            #pragma unroll
            for (int half = 0; half < 2; half++) {   // ks = 2m + half
                const unsigned aA[4] = {hmul2u(ha0, xa[2*half]), hmul2u(ha1, ya[2*half]),
                                        hmul2u(ha0, xa[2*half+1]), hmul2u(ha1, ya[2*half+1])};
                const unsigned aB[4] = {hmul2u(hb0, xb[2*half]), hmul2u(hb1, yb[2*half]),
                                        hmul2u(hb0, xb[2*half+1]), hmul2u(hb1, yb[2*half+1])};
                const uint4 bv = *(const uint4*)&sBt[((2*m + half) * 32 + lane) * 4];
                mma16816(accA[0], aA, bv.x, bv.y);
                mma16816(accA[1], aA, bv.z, bv.w);
                mma16816(accB[0], aB, bv.x, bv.y);
                mma16816(accB[1], aB, bv.z, bv.w);
            }
        }
    }
    #pragma unroll
    for (int half = 0; half < 2; half++) {   // bias ks = 32 + half
        const unsigned aA[4] = {xa[2*half], ya[2*half], xa[2*half+1], ya[2*half+1]};
        const unsigned aB[4] = {xb[2*half], yb[2*half], xb[2*half+1], yb[2*half+1]};
        const uint4 bv = *(const uint4*)&sBt[((32 + half) * 32 + lane) * 4];
        mma16816(accA[0], aA, bv.x, bv.y);
        mma16816(accA[1], aA, bv.z, bv.w);
        mma16816(accB[0], aB, bv.x, bv.y);
        mma16816(accB[1], aB, bv.z, bv.w);
    }

    const int dA0 = __shfl_sync(0xffffffffu, dst_reg, ra0);
    const int dA1 = __shfl_sync(0xffffffffu, dst_reg, ra1);
    const int dB0 = __shfl_sync(0xffffffffu, dst_reg, rb0);
    const int dB1 = __shfl_sync(0xffffffffu, dst_reg, rb1);
    #pragma unroll
    for (int t = 0; t < 2; t++) {
        const int o = t * 8 + k0;
        red_v2(&g_agg2[(size_t)dA0 * 16 + o], accA[t][0], accA[t][1]);
        red_v2(&g_agg2[(size_t)dA1 * 16 + o], accA[t][2], accA[t][3]);
        red_v2(&g_agg2[(size_t)dB0 * 16 + o], accB[t][0], accB[t][1]);
        red_v2(&g_agg2[(size_t)dB1 * 16 + o], accB[t][2], accB[t][3]);
    }
}

// ---------------- fused node2 + pool (sorted-batch atomic pairing) ----------------
__global__ void __launch_bounds__(256)
node2_pool_kernel(const int* __restrict__ batch,
                  const float* __restrict__ root2, const float* __restrict__ bias2)
{
    __shared__ float sR2[32 * 16];
    __shared__ float sB2v[16];
    for (int idx = threadIdx.x; idx < 512; idx += 256) sR2[idx] = root2[idx];
    if (threadIdx.x < 16) sB2v[threadIdx.x] = bias2[threadIdx.x];
    __syncthreads();

    const int w = (blockIdx.x * 256 + threadIdx.x) >> 5;
    const int lane = threadIdx.x & 31;
    const int half = lane >> 4;
    const int o = lane & 15;
    const int n = 2 * w + half;   // grid sized exactly: n < N_NODES always

    const unsigned hp = g_h1h2[(size_t)n * 16 + o];

    float acc = sB2v[o] + g_agg2[(size_t)n * 16 + o];
    #pragma unroll
    for (int i = 0; i < 16; i++) {
        const unsigned pi = __shfl_sync(0xffffffffu, hp, i, 16);
        const float2 f = __half22float2(*reinterpret_cast<const __half2*>(&pi));
        acc += f.x * sR2[(2 * i) * 16 + o] + f.y * sR2[(2 * i + 1) * 16 + o];
    }

    const float v = fmaxf(acc, 0.f);
    const int g = batch[n];
    const int g_other = __shfl_xor_sync(0xffffffffu, g, 16);
    const float v_other = __shfl_xor_sync(0xffffffffu, v, 16);
    if (g == g_other) {
        if (half == 0) {
            atomicAdd(&g_pool[g * 16 + o], v + v_other);
            if (o == 0) atomicAdd(&g_cnt[g], 2.0f);
        }
    } else {
        atomicAdd(&g_pool[g * 16 + o], v);
        if (o == 0) atomicAdd(&g_cnt[g], 1.0f);
    }
}

// ---------------- readout MLP ----------------
__global__ void readout_kernel(const float* __restrict__ l1w, const float* __restrict__ l1b,
                               const float* __restrict__ l2w, const float* __restrict__ l2b,
                               float* __restrict__ out)
{
    const int g = blockIdx.x * blockDim.x + threadIdx.x;
    if (g >= N_GRAPHS) return;
    const float inv = 1.0f / fmaxf(g_cnt[g], 1.0f);
    float p[16];
    #pragma unroll
    for (int o = 0; o < 16; o++) p[o] = g_pool[g * 16 + o] * inv;
    float acc = l2b[0];
    #pragma unroll
    for (int j = 0; j < 8; j++) {
        float s = l1b[j];
        #pragma unroll
        for (int o = 0; o < 16; o++) s += p[o] * l1w[o * 8 + j];
        acc += fmaxf(s, 0.f) * l2w[j];
    }
    out[g] = acc;
}

// ---------------- launch ----------------
extern "C" void kernel_launch(void* const* d_in, const int* in_sizes, int n_in,
                              void* d_out, int out_size)
{
    const float* x      = (const float*)d_in[0];
    const float* ea     = (const float*)d_in[1];
    const int*   ei     = (const int*)  d_in[2];
    const int*   batch  = (const int*)  d_in[3];
    const float* nn1_w1 = (const float*)d_in[4];
    const float* nn1_b1 = (const float*)d_in[5];
    const float* nn1_w2 = (const float*)d_in[6];
    const float* nn1_b2 = (const float*)d_in[7];
    const float* root1  = (const float*)d_in[8];
    const float* bias1  = (const float*)d_in[9];
    const float* nn2_w1 = (const float*)d_in[10];
    const float* nn2_b1 = (const float*)d_in[11];
    const float* nn2_w2 = (const float*)d_in[12];
    const float* nn2_b2 = (const float*)d_in[13];
    const float* root2  = (const float*)d_in[14];
    const float* bias2  = (const float*)d_in[15];
    const float* lin1_w = (const float*)d_in[16];
    const float* lin1_b = (const float*)d_in[17];
    const float* lin2_w = (const float*)d_in[18];
    const float* lin2_b = (const float*)d_in[19];
    float* out = (float*)d_out;

    // one prep pass: zero + xh2 + B tables (hid stays inline in edge kernels)
    prep_kernel<<<(N_NODES * 8 + 255) / 256, 256>>>(x, nn1_w2, nn1_b2, nn2_w2, nn2_b2);

    const int egrid = (WTILES1 + 7) / 8;   // 1563 blocks of 8 warp-tiles

    edge1_z_kernel<<<egrid, 256>>>(ea, ei, nn1_w1, nn1_b1);
    node1_kernel<<<N_NODES / 16, 256>>>(x, root1, bias1);
    edge2_z_kernel<<<egrid, 256>>>(ea, ei, nn2_w1, nn2_b1);
    node2_pool_kernel<<<(N_NODES / 2 * 32) / 256, 256>>>(batch, root2, bias2);
    readout_kernel<<<(N_GRAPHS + 255) / 256, 256>>>(lin1_w, lin1_b, lin2_w, lin2_b, out);
}